// round 15
// baseline (speedup 1.0000x reference)
#include <cuda_runtime.h>
#include <cuda_bf16.h>
#include <cstdint>

// ============================================================================
// AutoInt MHA — round 15: r14 + 40-row buffers + 6 CTAs/SM.
//  * All smem tiles shrunk to 40 rows (pads deleted). A-side over-reads into
//    neighbor buffers only feed DISCARDED C rows (MMA rows independent).
//    GEMM3's V k-rows 40-47 are the one poisoning hazard (0*NaN=NaN): VH
//    overflow = VL data (finite bf16), VL overflow = zeroed tail pad.
//  * T/V epilogue writes guarded r<40 so reg-garbage never escapes.
//  * smem 35,712 B + __launch_bounds__(128,6) -> 6 CTAs/SM, 24 warps.
//  * everything else identical to r14 (non-trans scores-B, phase-split
//    in-register softmax, residual->oacc, fragment-image weights via LDG).
// scores = X (Wq Wk^T) X^T (M precomputed). 3-term split: AhBh+AlBh+AhBl.
// ============================================================================

#define H_DIM 4

// ---- smem (bytes): six [40][72] bf16 tiles + 1152B zeroed tail pad ----
#define SM_XH  0u
#define SM_XL  5760u
#define SM_TH  11520u    // PH [40][56] aliases after softmax
#define SM_TL  17280u
#define SM_VH  23040u
#define SM_VL  28800u
#define SM_PAD 34560u    // zeroed: absorbs VL k-row 40-47 over-reads
#define SMEM_BYTES 35712u   // 6 CTAs/SM

// fragment image: [h][kt][nt] x 32 lanes x 16B  (nt: 0-7 T, 8-15 V, 16-23 R)
__device__ __align__(16) uint4 g_Bimg[H_DIM * 4 * 24 * 32];

// ---- PTX helpers -----------------------------------------------------------
__device__ __forceinline__ uint32_t cvta_smem(const void* p) {
    uint32_t a;
    asm("{ .reg .u64 t; cvta.to.shared.u64 t, %1; cvt.u32.u64 %0, t; }"
        : "=r"(a) : "l"(p));
    return a;
}
__device__ __forceinline__ void ldsm4(uint32_t a, uint32_t r[4]) {
    asm volatile("ldmatrix.sync.aligned.m8n8.x4.shared.b16 {%0,%1,%2,%3}, [%4];"
        : "=r"(r[0]), "=r"(r[1]), "=r"(r[2]), "=r"(r[3]) : "r"(a));
}
__device__ __forceinline__ void ldsm4t(uint32_t a, uint32_t r[4]) {
    asm volatile("ldmatrix.sync.aligned.m8n8.x4.trans.shared.b16 {%0,%1,%2,%3}, [%4];"
        : "=r"(r[0]), "=r"(r[1]), "=r"(r[2]), "=r"(r[3]) : "r"(a));
}
__device__ __forceinline__ void mma16816(float c[4], const uint32_t a[4],
                                         const uint32_t b0, const uint32_t b1) {
    asm volatile(
        "mma.sync.aligned.m16n8k16.row.col.f32.bf16.bf16.f32 "
        "{%0,%1,%2,%3}, {%4,%5,%6,%7}, {%8,%9}, {%0,%1,%2,%3};"
        : "+f"(c[0]), "+f"(c[1]), "+f"(c[2]), "+f"(c[3])
        : "r"(a[0]), "r"(a[1]), "r"(a[2]), "r"(a[3]), "r"(b0), "r"(b1));
}
__device__ __forceinline__ void split1(float x, float& h, float& l) {
    h = __bfloat162float(__float2bfloat16(x));
    l = x - h;
}
__device__ __forceinline__ uint32_t packh(float a, float b) {
    return (uint32_t)__bfloat16_as_ushort(__float2bfloat16(a)) |
           ((uint32_t)__bfloat16_as_ushort(__float2bfloat16(b)) << 16);
}
__device__ __forceinline__ uint32_t packl(float a, float b) {
    float ah = __bfloat162float(__float2bfloat16(a));
    float bh = __bfloat162float(__float2bfloat16(b));
    return packh(a - ah, b - bh);
}

// ----------------------------------------------------------------------------
// Precompute: M_h = Wq_h Wk_h^T; emit fragment-ordered hi/lo B image.
// ----------------------------------------------------------------------------
__global__ void precompute_kernel(const float* __restrict__ Wq,
                                  const float* __restrict__ Wk,
                                  const float* __restrict__ Wv,
                                  const float* __restrict__ Wres) {
    int h = blockIdx.x;
    __shared__ float sq[4096], sk[4096], sM[4096];
    for (int i = threadIdx.x; i < 4096; i += 256) {
        sq[i] = Wq[h * 4096 + i];
        sk[i] = Wk[h * 4096 + i];
    }
    __syncthreads();
    for (int idx = threadIdx.x; idx < 4096; idx += 256) {
        int e = idx >> 6, n = idx & 63;
        float s = 0.f;
        #pragma unroll 8
        for (int a = 0; a < 64; a++)
            s = fmaf(sq[e * 64 + a], sk[n * 64 + a], s);
        sM[e * 64 + n] = s;
    }
    __syncthreads();
    for (int t = threadIdx.x; t < 3072; t += 256) {
        int kt = t / 768, rem = t % 768;
        int nt = rem >> 5, lane = rem & 31;
        int gid = lane >> 2, tig = lane & 3;
        int n8 = nt * 8 + gid;
        int ks = kt * 16 + tig * 2;
        float v[4];
        #pragma unroll
        for (int q = 0; q < 4; q++) {
            int k = ks + (q >> 1) * 8 + (q & 1);
            float val;
            if (nt < 8)        val = sM[k * 64 + n8];
            else if (nt < 16)  val = Wv[h * 4096 + k * 64 + (n8 - 64)];
            else               val = Wres[k * 256 + h * 64 + (n8 - 128)];
            v[q] = val;
        }
        uint4 img;
        img.x = packh(v[0], v[1]);
        img.y = packh(v[2], v[3]);
        img.z = packl(v[0], v[1]);
        img.w = packl(v[2], v[3]);
        g_Bimg[((h * 4 + kt) * 24 + nt) * 32 + lane] = img;
    }
}

// ----------------------------------------------------------------------------
__global__ void __launch_bounds__(128, 6)
attn_main_kernel(const float* __restrict__ Xg, float* __restrict__ out) {
    extern __shared__ char sm[];
    const uint32_t sb = cvta_smem(sm);

    const int tid  = threadIdx.x;
    const int w    = tid >> 5;          // warp 0-3
    const int lane = tid & 31;
    const int b    = blockIdx.x >> 1;   // batch
    const int hp   = blockIdx.x & 1;    // head pair
    const int lr   = lane & 15;
    const int lq   = lane >> 4;
    const int row4 = lane >> 2;
    const int col2 = 2 * (lane & 3);

    // ---- zero tail pad (absorbs VL k-row 40-47 over-reads; must be finite) --
    for (int i = tid; i < 72; i += 128)
        *(uint4*)(sm + SM_PAD + i * 16) = make_uint4(0, 0, 0, 0);

    // ---- stage X split hi/lo (rows 0-39 only; no pads) ----
    {
        const float4* xb = reinterpret_cast<const float4*>(Xg + (size_t)b * 2560);
        __nv_bfloat16* XH = (__nv_bfloat16*)(sm + SM_XH);
        __nv_bfloat16* XL = (__nv_bfloat16*)(sm + SM_XL);
        for (int i = tid; i < 640; i += 128) {
            float4 v = xb[i];
            int f = i >> 4, e0 = (i & 15) * 4;
            float vv[4] = {v.x, v.y, v.z, v.w};
            #pragma unroll
            for (int j = 0; j < 4; j++) {
                float hi, lo;
                split1(vv[j], hi, lo);
                XH[f * 72 + e0 + j] = __float2bfloat16(hi);
                XL[f * 72 + e0 + j] = __float2bfloat16(lo);
            }
        }
    }
    __syncthreads();

    for (int hh = 0; hh < 2; hh++) {
        const int h = hp * 2 + hh;

        // ==== GEMM1: T|V = X @ [M|Wv]  (B frags via LDG, L2-resident) ====
        float tac[3][2][4], vac[3][2][4];
        #pragma unroll
        for (int mt = 0; mt < 3; mt++)
            #pragma unroll
            for (int jj = 0; jj < 2; jj++)
                #pragma unroll
                for (int q = 0; q < 4; q++)
                    tac[mt][jj][q] = vac[mt][jj][q] = 0.f;
        #pragma unroll
        for (int kt = 0; kt < 4; kt++) {
            uint32_t ah[3][4], al[3][4];
            #pragma unroll
            for (int mt = 0; mt < 3; mt++) {
                uint32_t a0 = sb + SM_XH + ((mt * 16 + lr) * 72 + kt * 16) * 2 + (lq << 4);
                ldsm4(a0, ah[mt]);
                ldsm4(a0 + (SM_XL - SM_XH), al[mt]);
            }
            #pragma unroll
            for (int mat = 0; mat < 2; mat++) {
                #pragma unroll
                for (int jj = 0; jj < 2; jj++) {
                    int nt = mat * 8 + 2 * w + jj;
                    uint4 bb = g_Bimg[((h * 4 + kt) * 24 + nt) * 32 + lane];
                    #pragma unroll
                    for (int mt = 0; mt < 3; mt++) {
                        float* c = (mat == 0) ? tac[mt][jj] : vac[mt][jj];
                        mma16816(c, ah[mt], bb.x, bb.y);
                        mma16816(c, al[mt], bb.x, bb.y);
                        mma16816(c, ah[mt], bb.z, bb.w);
                    }
                }
            }
        }
        // epilogue: T,V rows <40 -> smem split (garbage rows never escape)
        #pragma unroll
        for (int jj = 0; jj < 2; jj++) {
            int c = 16 * w + 8 * jj + col2;
            #pragma unroll
            for (int mt = 0; mt < 3; mt++) {
                int r0 = mt * 16 + row4, r1 = r0 + 8;
                const float* tt = tac[mt][jj];
                const float* vv = vac[mt][jj];
                *(uint32_t*)(sm + SM_TH + (r0 * 72 + c) * 2) = packh(tt[0], tt[1]);
                *(uint32_t*)(sm + SM_TL + (r0 * 72 + c) * 2) = packl(tt[0], tt[1]);
                *(uint32_t*)(sm + SM_VH + (r0 * 72 + c) * 2) = packh(vv[0], vv[1]);
                *(uint32_t*)(sm + SM_VL + (r0 * 72 + c) * 2) = packl(vv[0], vv[1]);
                if (r1 < 40) {
                    *(uint32_t*)(sm + SM_TH + (r1 * 72 + c) * 2) = packh(tt[2], tt[3]);
                    *(uint32_t*)(sm + SM_TL + (r1 * 72 + c) * 2) = packl(tt[2], tt[3]);
                    *(uint32_t*)(sm + SM_VH + (r1 * 72 + c) * 2) = packh(vv[2], vv[3]);
                    *(uint32_t*)(sm + SM_VL + (r1 * 72 + c) * 2) = packl(vv[2], vv[3]);
                }
            }
        }

        // ==== residual pass: oacc = X @ WresBlk (independent of T/V) ====
        float oacc[3][2][4];
        #pragma unroll
        for (int mt = 0; mt < 3; mt++)
            #pragma unroll
            for (int jj = 0; jj < 2; jj++)
                #pragma unroll
                for (int q = 0; q < 4; q++) oacc[mt][jj][q] = 0.f;
        #pragma unroll
        for (int kt = 0; kt < 4; kt++) {
            uint4 bb0 = g_Bimg[((h * 4 + kt) * 24 + 16 + 2 * w) * 32 + lane];
            uint4 bb1 = g_Bimg[((h * 4 + kt) * 24 + 17 + 2 * w) * 32 + lane];
            #pragma unroll
            for (int mt = 0; mt < 3; mt++) {
                uint32_t ah[4], al[4];
                uint32_t a0 = sb + SM_XH + ((mt * 16 + lr) * 72 + kt * 16) * 2 + (lq << 4);
                ldsm4(a0, ah);
                ldsm4(a0 + (SM_XL - SM_XH), al);
                mma16816(oacc[mt][0], ah, bb0.x, bb0.y);
                mma16816(oacc[mt][0], al, bb0.x, bb0.y);
                mma16816(oacc[mt][0], ah, bb0.z, bb0.w);
                mma16816(oacc[mt][1], ah, bb1.x, bb1.y);
                mma16816(oacc[mt][1], al, bb1.x, bb1.y);
                mma16816(oacc[mt][1], ah, bb1.z, bb1.w);
            }
        }
        __syncthreads();   // GEMM1 epilogue visible before scores reads

        // ==== PHASE A (warps 0-2): scores MMAs + softmax COMPUTE (regs) ====
        float sacc[5][4];
        float inv0 = 0.f, inv1 = 0.f;
        if (w < 3) {
            #pragma unroll
            for (int j = 0; j < 5; j++)
                #pragma unroll
                for (int q = 0; q < 4; q++) sacc[j][q] = 0.f;
            #pragma unroll
            for (int kt = 0; kt < 4; kt++) {
                uint32_t ah[4], al[4];
                uint32_t a0 = sb + SM_TH + ((w * 16 + lr) * 72 + kt * 16) * 2 + (lq << 4);
                ldsm4(a0, ah);
                ldsm4(a0 + (SM_TL - SM_TH), al);
                #pragma unroll
                for (int j = 0; j < 5; j++) {
                    // non-trans B: X rows are col-major B frags for T @ X^T
                    uint32_t bt[4];
                    uint32_t badr = sb + ((lane < 16) ? SM_XH : SM_XL) +
                        ((8 * j + (lane & 7)) * 72 + kt * 16 + ((lane >> 3) & 1) * 8) * 2;
                    ldsm4(badr, bt);
                    mma16816(sacc[j], ah, bt[0], bt[1]);
                    mma16816(sacc[j], al, bt[0], bt[1]);
                    mma16816(sacc[j], ah, bt[2], bt[3]);
                }
            }
            float m0 = -3.4e38f, m1 = -3.4e38f;
            #pragma unroll
            for (int j = 0; j < 5; j++) {
                m0 = fmaxf(m0, fmaxf(sacc[j][0], sacc[j][1]));
                m1 = fmaxf(m1, fmaxf(sacc[j][2], sacc[j][3]));
            }
            m0 = fmaxf(m0, __shfl_xor_sync(0xffffffffu, m0, 1));
            m0 = fmaxf(m0, __shfl_xor_sync(0xffffffffu, m0, 2));
            m1 = fmaxf(m1, __shfl_xor_sync(0xffffffffu, m1, 1));
            m1 = fmaxf(m1, __shfl_xor_sync(0xffffffffu, m1, 2));
            float s0 = 0.f, s1 = 0.f;
            #pragma unroll
            for (int j = 0; j < 5; j++) {
                sacc[j][0] = __expf(sacc[j][0] - m0);
                sacc[j][1] = __expf(sacc[j][1] - m0);
                sacc[j][2] = __expf(sacc[j][2] - m1);
                sacc[j][3] = __expf(sacc[j][3] - m1);
                s0 += sacc[j][0] + sacc[j][1];
                s1 += sacc[j][2] + sacc[j][3];
            }
            s0 += __shfl_xor_sync(0xffffffffu, s0, 1);
            s0 += __shfl_xor_sync(0xffffffffu, s0, 2);
            s1 += __shfl_xor_sync(0xffffffffu, s1, 1);
            s1 += __shfl_xor_sync(0xffffffffu, s1, 2);
            inv0 = 1.f / s0;
            inv1 = 1.f / s1;
        }
        __syncthreads();   // race fix: all TH/TL reads done before PH writes

        // ==== PHASE B (warps 0-2): write PH/PL (aliases TH/TL) ====
        if (w < 3) {
            int r0 = 16 * w + row4, r1 = r0 + 8;
            bool has1 = (r1 < 40);
            #pragma unroll
            for (int j = 0; j < 5; j++) {
                int c = 8 * j + col2;
                float p0 = sacc[j][0] * inv0, p0b = sacc[j][1] * inv0;
                *(uint32_t*)(sm + SM_TH + (r0 * 56 + c) * 2) = packh(p0, p0b);
                *(uint32_t*)(sm + SM_TL + (r0 * 56 + c) * 2) = packl(p0, p0b);
                if (has1) {
                    float p1 = sacc[j][2] * inv1, p1b = sacc[j][3] * inv1;
                    *(uint32_t*)(sm + SM_TH + (r1 * 56 + c) * 2) = packh(p1, p1b);
                    *(uint32_t*)(sm + SM_TL + (r1 * 56 + c) * 2) = packl(p1, p1b);
                }
            }
            {   // zero attn k-pad cols 40-47
                int c = 40 + col2;
                *(uint32_t*)(sm + SM_TH + (r0 * 56 + c) * 2) = 0u;
                *(uint32_t*)(sm + SM_TL + (r0 * 56 + c) * 2) = 0u;
                if (has1) {
                    *(uint32_t*)(sm + SM_TH + (r1 * 56 + c) * 2) = 0u;
                    *(uint32_t*)(sm + SM_TL + (r1 * 56 + c) * 2) = 0u;
                }
            }
        }
        __syncthreads();

        // ==== GEMM3: oacc += attn @ V ; relu ; store ====
        #pragma unroll
        for (int kt = 0; kt < 3; kt++) {
            uint32_t ah[3][4], al[3][4];
            #pragma unroll
            for (int mt = 0; mt < 3; mt++) {
                uint32_t a0 = sb + SM_TH + ((mt * 16 + lr) * 56 + kt * 16) * 2 + (lq << 4);
                ldsm4(a0, ah[mt]);
                ldsm4(a0 + (SM_TL - SM_TH), al[mt]);
            }
            #pragma unroll
            for (int jj = 0; jj < 2; jj++) {
                int nc = 16 * w + 8 * jj;
                uint32_t bt[4];
                uint32_t badr = sb + ((lane < 16) ? SM_VH : SM_VL) +
                                ((kt * 16 + lr) * 72 + nc) * 2;
                ldsm4t(badr, bt);
                #pragma unroll
                for (int mt = 0; mt < 3; mt++) {
                    mma16816(oacc[mt][jj], ah[mt], bt[0], bt[1]);
                    mma16816(oacc[mt][jj], al[mt], bt[0], bt[1]);
                    mma16816(oacc[mt][jj], ah[mt], bt[2], bt[3]);
                }
            }
        }
        {
            float* ob = out + (size_t)b * (40 * 256) + h * 64;
            #pragma unroll
            for (int jj = 0; jj < 2; jj++) {
                int c = 16 * w + 8 * jj + col2;
                #pragma unroll
                for (int mt = 0; mt < 3; mt++) {
                    int r0 = mt * 16 + row4, r1 = r0 + 8;
                    const float* oa = oacc[mt][jj];
                    *(float2*)(ob + r0 * 256 + c) =
                        make_float2(fmaxf(oa[0], 0.f), fmaxf(oa[1], 0.f));
                    if (r1 < 40)
                        *(float2*)(ob + r1 * 256 + c) =
                            make_float2(fmaxf(oa[2], 0.f), fmaxf(oa[3], 0.f));
                }
            }
        }
        __syncthreads();   // protect TH/TL/VH/VL before next head's GEMM1
    }
}

// ----------------------------------------------------------------------------
extern "C" void kernel_launch(void* const* d_in, const int* in_sizes, int n_in,
                              void* d_out, int out_size) {
    const float* X    = (const float*)d_in[0];
    const float* Wq   = (const float*)d_in[1];
    const float* Wk   = (const float*)d_in[2];
    const float* Wv   = (const float*)d_in[3];
    const float* Wres = (const float*)d_in[4];
    float* out = (float*)d_out;

    cudaFuncSetAttribute(attn_main_kernel,
                         cudaFuncAttributeMaxDynamicSharedMemorySize, SMEM_BYTES);

    precompute_kernel<<<H_DIM, 256>>>(Wq, Wk, Wv, Wres);
    attn_main_kernel<<<8192, 128, SMEM_BYTES>>>(X, out);
}

// round 16
// speedup vs baseline: 1.3535x; 1.3535x over previous
#include <cuda_runtime.h>
#include <cuda_bf16.h>
#include <cstdint>

// ============================================================================
// AutoInt MHA — round 16: r15 + GEMM1 split into T-pass / V-pass.
// r15 regressed from register SPILLS (DRAM 2->28%): (128,6) cap 85 vs true
// live set ~96 in fused GEMM1 (48 accs + 24 A-frags). Fix: compute T and V
// sequentially (24 accs + 24 frags each, peak ~65) so 6 CTAs fit honestly.
// Cost: one extra A-frag load pass per head (~24 ldsm4) — noise vs spills.
//  * 40-row buffers, smem 35,712 B, 6 CTAs/SM, 24 warps.
//  * non-trans scores-B from XH/XL; phase-split in-register softmax;
//    residual accumulated into GEMM3's oacc; weights via fragment image LDG.
// scores = X (Wq Wk^T) X^T (M precomputed). 3-term split: AhBh+AlBh+AhBl.
// ============================================================================

#define H_DIM 4

// ---- smem (bytes): six [40][72] bf16 tiles + 1152B zeroed tail pad ----
#define SM_XH  0u
#define SM_XL  5760u
#define SM_TH  11520u    // PH [40][56] aliases after softmax
#define SM_TL  17280u
#define SM_VH  23040u
#define SM_VL  28800u
#define SM_PAD 34560u    // zeroed: absorbs VL k-row 40-47 over-reads
#define SMEM_BYTES 35712u   // 6 CTAs/SM

// fragment image: [h][kt][nt] x 32 lanes x 16B  (nt: 0-7 T, 8-15 V, 16-23 R)
__device__ __align__(16) uint4 g_Bimg[H_DIM * 4 * 24 * 32];

// ---- PTX helpers -----------------------------------------------------------
__device__ __forceinline__ uint32_t cvta_smem(const void* p) {
    uint32_t a;
    asm("{ .reg .u64 t; cvta.to.shared.u64 t, %1; cvt.u32.u64 %0, t; }"
        : "=r"(a) : "l"(p));
    return a;
}
__device__ __forceinline__ void ldsm4(uint32_t a, uint32_t r[4]) {
    asm volatile("ldmatrix.sync.aligned.m8n8.x4.shared.b16 {%0,%1,%2,%3}, [%4];"
        : "=r"(r[0]), "=r"(r[1]), "=r"(r[2]), "=r"(r[3]) : "r"(a));
}
__device__ __forceinline__ void ldsm4t(uint32_t a, uint32_t r[4]) {
    asm volatile("ldmatrix.sync.aligned.m8n8.x4.trans.shared.b16 {%0,%1,%2,%3}, [%4];"
        : "=r"(r[0]), "=r"(r[1]), "=r"(r[2]), "=r"(r[3]) : "r"(a));
}
__device__ __forceinline__ void mma16816(float c[4], const uint32_t a[4],
                                         const uint32_t b0, const uint32_t b1) {
    asm volatile(
        "mma.sync.aligned.m16n8k16.row.col.f32.bf16.bf16.f32 "
        "{%0,%1,%2,%3}, {%4,%5,%6,%7}, {%8,%9}, {%0,%1,%2,%3};"
        : "+f"(c[0]), "+f"(c[1]), "+f"(c[2]), "+f"(c[3])
        : "r"(a[0]), "r"(a[1]), "r"(a[2]), "r"(a[3]), "r"(b0), "r"(b1));
}
__device__ __forceinline__ void split1(float x, float& h, float& l) {
    h = __bfloat162float(__float2bfloat16(x));
    l = x - h;
}
__device__ __forceinline__ uint32_t packh(float a, float b) {
    return (uint32_t)__bfloat16_as_ushort(__float2bfloat16(a)) |
           ((uint32_t)__bfloat16_as_ushort(__float2bfloat16(b)) << 16);
}
__device__ __forceinline__ uint32_t packl(float a, float b) {
    float ah = __bfloat162float(__float2bfloat16(a));
    float bh = __bfloat162float(__float2bfloat16(b));
    return packh(a - ah, b - bh);
}

// ----------------------------------------------------------------------------
// Precompute: M_h = Wq_h Wk_h^T; emit fragment-ordered hi/lo B image.
// ----------------------------------------------------------------------------
__global__ void precompute_kernel(const float* __restrict__ Wq,
                                  const float* __restrict__ Wk,
                                  const float* __restrict__ Wv,
                                  const float* __restrict__ Wres) {
    int h = blockIdx.x;
    __shared__ float sq[4096], sk[4096], sM[4096];
    for (int i = threadIdx.x; i < 4096; i += 256) {
        sq[i] = Wq[h * 4096 + i];
        sk[i] = Wk[h * 4096 + i];
    }
    __syncthreads();
    for (int idx = threadIdx.x; idx < 4096; idx += 256) {
        int e = idx >> 6, n = idx & 63;
        float s = 0.f;
        #pragma unroll 8
        for (int a = 0; a < 64; a++)
            s = fmaf(sq[e * 64 + a], sk[n * 64 + a], s);
        sM[e * 64 + n] = s;
    }
    __syncthreads();
    for (int t = threadIdx.x; t < 3072; t += 256) {
        int kt = t / 768, rem = t % 768;
        int nt = rem >> 5, lane = rem & 31;
        int gid = lane >> 2, tig = lane & 3;
        int n8 = nt * 8 + gid;
        int ks = kt * 16 + tig * 2;
        float v[4];
        #pragma unroll
        for (int q = 0; q < 4; q++) {
            int k = ks + (q >> 1) * 8 + (q & 1);
            float val;
            if (nt < 8)        val = sM[k * 64 + n8];
            else if (nt < 16)  val = Wv[h * 4096 + k * 64 + (n8 - 64)];
            else               val = Wres[k * 256 + h * 64 + (n8 - 128)];
            v[q] = val;
        }
        uint4 img;
        img.x = packh(v[0], v[1]);
        img.y = packh(v[2], v[3]);
        img.z = packl(v[0], v[1]);
        img.w = packl(v[2], v[3]);
        g_Bimg[((h * 4 + kt) * 24 + nt) * 32 + lane] = img;
    }
}

// ----------------------------------------------------------------------------
__global__ void __launch_bounds__(128, 6)
attn_main_kernel(const float* __restrict__ Xg, float* __restrict__ out) {
    extern __shared__ char sm[];
    const uint32_t sb = cvta_smem(sm);

    const int tid  = threadIdx.x;
    const int w    = tid >> 5;          // warp 0-3
    const int lane = tid & 31;
    const int b    = blockIdx.x >> 1;   // batch
    const int hp   = blockIdx.x & 1;    // head pair
    const int lr   = lane & 15;
    const int lq   = lane >> 4;
    const int row4 = lane >> 2;
    const int col2 = 2 * (lane & 3);

    // ---- zero tail pad (absorbs VL k-row 40-47 over-reads; must be finite) --
    for (int i = tid; i < 72; i += 128)
        *(uint4*)(sm + SM_PAD + i * 16) = make_uint4(0, 0, 0, 0);

    // ---- stage X split hi/lo (rows 0-39 only) ----
    {
        const float4* xb = reinterpret_cast<const float4*>(Xg + (size_t)b * 2560);
        __nv_bfloat16* XH = (__nv_bfloat16*)(sm + SM_XH);
        __nv_bfloat16* XL = (__nv_bfloat16*)(sm + SM_XL);
        for (int i = tid; i < 640; i += 128) {
            float4 v = xb[i];
            int f = i >> 4, e0 = (i & 15) * 4;
            float vv[4] = {v.x, v.y, v.z, v.w};
            #pragma unroll
            for (int j = 0; j < 4; j++) {
                float hi, lo;
                split1(vv[j], hi, lo);
                XH[f * 72 + e0 + j] = __float2bfloat16(hi);
                XL[f * 72 + e0 + j] = __float2bfloat16(lo);
            }
        }
    }
    __syncthreads();

    for (int hh = 0; hh < 2; hh++) {
        const int h = hp * 2 + hh;

        // ==== GEMM1 split: mat 0 -> T, mat 1 -> V (peak 24 accs + 24 frags) ==
        #pragma unroll
        for (int mat = 0; mat < 2; mat++) {
            float acc[3][2][4];
            #pragma unroll
            for (int mt = 0; mt < 3; mt++)
                #pragma unroll
                for (int jj = 0; jj < 2; jj++)
                    #pragma unroll
                    for (int q = 0; q < 4; q++) acc[mt][jj][q] = 0.f;
            #pragma unroll
            for (int kt = 0; kt < 4; kt++) {
                uint32_t ah[3][4], al[3][4];
                #pragma unroll
                for (int mt = 0; mt < 3; mt++) {
                    uint32_t a0 = sb + SM_XH + ((mt * 16 + lr) * 72 + kt * 16) * 2 + (lq << 4);
                    ldsm4(a0, ah[mt]);
                    ldsm4(a0 + (SM_XL - SM_XH), al[mt]);
                }
                #pragma unroll
                for (int jj = 0; jj < 2; jj++) {
                    int nt = mat * 8 + 2 * w + jj;
                    uint4 bb = g_Bimg[((h * 4 + kt) * 24 + nt) * 32 + lane];
                    #pragma unroll
                    for (int mt = 0; mt < 3; mt++) {
                        mma16816(acc[mt][jj], ah[mt], bb.x, bb.y);
                        mma16816(acc[mt][jj], al[mt], bb.x, bb.y);
                        mma16816(acc[mt][jj], ah[mt], bb.z, bb.w);
                    }
                }
            }
            // epilogue: rows <40 -> smem split
            uint32_t dH = (mat == 0) ? SM_TH : SM_VH;
            uint32_t dL = (mat == 0) ? SM_TL : SM_VL;
            #pragma unroll
            for (int jj = 0; jj < 2; jj++) {
                int c = 16 * w + 8 * jj + col2;
                #pragma unroll
                for (int mt = 0; mt < 3; mt++) {
                    int r0 = mt * 16 + row4, r1 = r0 + 8;
                    const float* aa = acc[mt][jj];
                    *(uint32_t*)(sm + dH + (r0 * 72 + c) * 2) = packh(aa[0], aa[1]);
                    *(uint32_t*)(sm + dL + (r0 * 72 + c) * 2) = packl(aa[0], aa[1]);
                    if (r1 < 40) {
                        *(uint32_t*)(sm + dH + (r1 * 72 + c) * 2) = packh(aa[2], aa[3]);
                        *(uint32_t*)(sm + dL + (r1 * 72 + c) * 2) = packl(aa[2], aa[3]);
                    }
                }
            }
        }

        // ==== residual pass: oacc = X @ WresBlk ====
        float oacc[3][2][4];
        #pragma unroll
        for (int mt = 0; mt < 3; mt++)
            #pragma unroll
            for (int jj = 0; jj < 2; jj++)
                #pragma unroll
                for (int q = 0; q < 4; q++) oacc[mt][jj][q] = 0.f;
        #pragma unroll
        for (int kt = 0; kt < 4; kt++) {
            uint4 bb0 = g_Bimg[((h * 4 + kt) * 24 + 16 + 2 * w) * 32 + lane];
            uint4 bb1 = g_Bimg[((h * 4 + kt) * 24 + 17 + 2 * w) * 32 + lane];
            #pragma unroll
            for (int mt = 0; mt < 3; mt++) {
                uint32_t ah[4], al[4];
                uint32_t a0 = sb + SM_XH + ((mt * 16 + lr) * 72 + kt * 16) * 2 + (lq << 4);
                ldsm4(a0, ah);
                ldsm4(a0 + (SM_XL - SM_XH), al);
                mma16816(oacc[mt][0], ah, bb0.x, bb0.y);
                mma16816(oacc[mt][0], al, bb0.x, bb0.y);
                mma16816(oacc[mt][0], ah, bb0.z, bb0.w);
                mma16816(oacc[mt][1], ah, bb1.x, bb1.y);
                mma16816(oacc[mt][1], al, bb1.x, bb1.y);
                mma16816(oacc[mt][1], ah, bb1.z, bb1.w);
            }
        }
        __syncthreads();   // GEMM1 epilogue visible before scores reads

        // ==== PHASE A (warps 0-2): scores MMAs + softmax COMPUTE (regs) ====
        float sacc[5][4];
        float inv0 = 0.f, inv1 = 0.f;
        if (w < 3) {
            #pragma unroll
            for (int j = 0; j < 5; j++)
                #pragma unroll
                for (int q = 0; q < 4; q++) sacc[j][q] = 0.f;
            #pragma unroll
            for (int kt = 0; kt < 4; kt++) {
                uint32_t ah[4], al[4];
                uint32_t a0 = sb + SM_TH + ((w * 16 + lr) * 72 + kt * 16) * 2 + (lq << 4);
                ldsm4(a0, ah);
                ldsm4(a0 + (SM_TL - SM_TH), al);
                #pragma unroll
                for (int j = 0; j < 5; j++) {
                    // non-trans B: X rows are col-major B frags for T @ X^T
                    uint32_t bt[4];
                    uint32_t badr = sb + ((lane < 16) ? SM_XH : SM_XL) +
                        ((8 * j + (lane & 7)) * 72 + kt * 16 + ((lane >> 3) & 1) * 8) * 2;
                    ldsm4(badr, bt);
                    mma16816(sacc[j], ah, bt[0], bt[1]);
                    mma16816(sacc[j], al, bt[0], bt[1]);
                    mma16816(sacc[j], ah, bt[2], bt[3]);
                }
            }
            float m0 = -3.4e38f, m1 = -3.4e38f;
            #pragma unroll
            for (int j = 0; j < 5; j++) {
                m0 = fmaxf(m0, fmaxf(sacc[j][0], sacc[j][1]));
                m1 = fmaxf(m1, fmaxf(sacc[j][2], sacc[j][3]));
            }
            m0 = fmaxf(m0, __shfl_xor_sync(0xffffffffu, m0, 1));
            m0 = fmaxf(m0, __shfl_xor_sync(0xffffffffu, m0, 2));
            m1 = fmaxf(m1, __shfl_xor_sync(0xffffffffu, m1, 1));
            m1 = fmaxf(m1, __shfl_xor_sync(0xffffffffu, m1, 2));
            float s0 = 0.f, s1 = 0.f;
            #pragma unroll
            for (int j = 0; j < 5; j++) {
                sacc[j][0] = __expf(sacc[j][0] - m0);
                sacc[j][1] = __expf(sacc[j][1] - m0);
                sacc[j][2] = __expf(sacc[j][2] - m1);
                sacc[j][3] = __expf(sacc[j][3] - m1);
                s0 += sacc[j][0] + sacc[j][1];
                s1 += sacc[j][2] + sacc[j][3];
            }
            s0 += __shfl_xor_sync(0xffffffffu, s0, 1);
            s0 += __shfl_xor_sync(0xffffffffu, s0, 2);
            s1 += __shfl_xor_sync(0xffffffffu, s1, 1);
            s1 += __shfl_xor_sync(0xffffffffu, s1, 2);
            inv0 = 1.f / s0;
            inv1 = 1.f / s1;
        }
        __syncthreads();   // race fix: all TH/TL reads done before PH writes

        // ==== PHASE B (warps 0-2): write PH/PL (aliases TH/TL) ====
        if (w < 3) {
            int r0 = 16 * w + row4, r1 = r0 + 8;
            bool has1 = (r1 < 40);
            #pragma unroll
            for (int j = 0; j < 5; j++) {
                int c = 8 * j + col2;
                float p0 = sacc[j][0] * inv0, p0b = sacc[j][1] * inv0;
                *(uint32_t*)(sm + SM_TH + (r0 * 56 + c) * 2) = packh(p0, p0b);
                *(uint32_t*)(sm + SM_TL + (r0 * 56 + c) * 2) = packl(p0, p0b);
                if (has1) {
                    float p1 = sacc[j][2] * inv1, p1b = sacc[j][3] * inv1;
                    *(uint32_t*)(sm + SM_TH + (r1 * 56 + c) * 2) = packh(p1, p1b);
                    *(uint32_t*)(sm + SM_TL + (r1 * 56 + c) * 2) = packl(p1, p1b);
                }
            }
            {   // zero attn k-pad cols 40-47
                int c = 40 + col2;
                *(uint32_t*)(sm + SM_TH + (r0 * 56 + c) * 2) = 0u;
                *(uint32_t*)(sm + SM_TL + (r0 * 56 + c) * 2) = 0u;
                if (has1) {
                    *(uint32_t*)(sm + SM_TH + (r1 * 56 + c) * 2) = 0u;
                    *(uint32_t*)(sm + SM_TL + (r1 * 56 + c) * 2) = 0u;
                }
            }
        }
        __syncthreads();

        // ==== GEMM3: oacc += attn @ V ; relu ; store ====
        #pragma unroll
        for (int kt = 0; kt < 3; kt++) {
            uint32_t ah[3][4], al[3][4];
            #pragma unroll
            for (int mt = 0; mt < 3; mt++) {
                uint32_t a0 = sb + SM_TH + ((mt * 16 + lr) * 56 + kt * 16) * 2 + (lq << 4);
                ldsm4(a0, ah[mt]);
                ldsm4(a0 + (SM_TL - SM_TH), al[mt]);
            }
            #pragma unroll
            for (int jj = 0; jj < 2; jj++) {
                int nc = 16 * w + 8 * jj;
                uint32_t bt[4];
                uint32_t badr = sb + ((lane < 16) ? SM_VH : SM_VL) +
                                ((kt * 16 + lr) * 72 + nc) * 2;
                ldsm4t(badr, bt);
                #pragma unroll
                for (int mt = 0; mt < 3; mt++) {
                    mma16816(oacc[mt][jj], ah[mt], bt[0], bt[1]);
                    mma16816(oacc[mt][jj], al[mt], bt[0], bt[1]);
                    mma16816(oacc[mt][jj], ah[mt], bt[2], bt[3]);
                }
            }
        }
        {
            float* ob = out + (size_t)b * (40 * 256) + h * 64;
            #pragma unroll
            for (int jj = 0; jj < 2; jj++) {
                int c = 16 * w + 8 * jj + col2;
                #pragma unroll
                for (int mt = 0; mt < 3; mt++) {
                    int r0 = mt * 16 + row4, r1 = r0 + 8;
                    const float* oa = oacc[mt][jj];
                    *(float2*)(ob + r0 * 256 + c) =
                        make_float2(fmaxf(oa[0], 0.f), fmaxf(oa[1], 0.f));
                    if (r1 < 40)
                        *(float2*)(ob + r1 * 256 + c) =
                            make_float2(fmaxf(oa[2], 0.f), fmaxf(oa[3], 0.f));
                }
            }
        }
        __syncthreads();   // protect TH/TL/VH/VL before next head's GEMM1
    }
}

// ----------------------------------------------------------------------------
extern "C" void kernel_launch(void* const* d_in, const int* in_sizes, int n_in,
                              void* d_out, int out_size) {
    const float* X    = (const float*)d_in[0];
    const float* Wq   = (const float*)d_in[1];
    const float* Wk   = (const float*)d_in[2];
    const float* Wv   = (const float*)d_in[3];
    const float* Wres = (const float*)d_in[4];
    float* out = (float*)d_out;

    cudaFuncSetAttribute(attn_main_kernel,
                         cudaFuncAttributeMaxDynamicSharedMemorySize, SMEM_BYTES);

    precompute_kernel<<<H_DIM, 256>>>(Wq, Wk, Wv, Wres);
    attn_main_kernel<<<8192, 128, SMEM_BYTES>>>(X, out);
}